// round 10
// baseline (speedup 1.0000x reference)
#include <cuda_runtime.h>

// Problem constants
#define BATCH  1024
#define FDIM   128
#define EDIM   256
#define HEADS  8
#define DHEAD  32
#define MROWS  (BATCH * FDIM)   // 131072

// Scratch for Q, K, V, R projections: 4 * 131072 * 256 floats = 512 MB.
__device__ float g_QKVR[(size_t)4 * MROWS * EDIM];

typedef unsigned long long u64;

// ---- packed fp32 (FFMA2) helpers -----------------------------------------
__device__ __forceinline__ u64 pack2(float lo, float hi) {
    u64 r;
    asm("mov.b64 %0, {%1, %2};" : "=l"(r) : "f"(lo), "f"(hi));
    return r;
}
__device__ __forceinline__ void fma2(u64& d, u64 a, u64 b) {
    asm("fma.rn.f32x2 %0, %1, %2, %3;" : "=l"(d) : "l"(a), "l"(b), "l"(d));
}
__device__ __forceinline__ float2 unpack2(u64 v) {
    float2 f;
    asm("mov.b64 {%0, %1}, %2;" : "=f"(f.x), "=f"(f.y) : "l"(v));
    return f;
}

// ---------------------------------------------------------------------------
// Kernel 1: projections.  C[128x64 tile] = X[128x256] @ W[256x64-slice]
// Grid (16,1024), 256 threads, 2 CTAs/SM.  K chunked by 32, double-buffered.
// sA stored TRANSPOSED (k-major [32][132]) so A-fragments load as row-pairs
// (ulonglong2) feeding fma.rn.f32x2 directly.  Thread tile 8x4, acc = 4 row-
// pairs x 4 cols of packed f32x2.
// ---------------------------------------------------------------------------
constexpr int K1_SAP = 132;  // sA^T pitch: 128 rows + 4 pad
constexpr int K1_SBP = 68;   // sB pitch: 64 cols + 4 pad
constexpr int K1_SMEM = (2 * 32 * K1_SAP + 2 * 32 * K1_SBP) * 4;  // 51200 B

__global__ void __launch_bounds__(256, 2)
proj_kernel(const float* __restrict__ X,
            const float* __restrict__ Wq, const float* __restrict__ Wk,
            const float* __restrict__ Wv, const float* __restrict__ Wr)
{
    extern __shared__ float sm1[];
    float* sA = sm1;                      // [2][32 k][132 rows]
    float* sB = sm1 + 2 * 32 * K1_SAP;    // [2][32 k][68 cols]

    const int t    = threadIdx.x;
    const int bx   = blockIdx.x;
    const int m0   = blockIdx.y * 128;
    const int widx = bx >> 2;
    const int jo   = (bx & 3) * 64;
    const float* W = (widx == 0) ? Wq : (widx == 1) ? Wk : (widx == 2) ? Wv : Wr;
    float* out = g_QKVR + (size_t)widx * MROWS * EDIM;

    const int ti = t >> 4;   // 0..15 -> rows 8*ti..8*ti+7
    const int tj = t & 15;   // 0..15 -> cols 4*tj..4*tj+3

    const int ar = t >> 3, ac = t & 7;    // A stage: 128 rows x 8 float4
    const int br = t >> 4, bc = t & 15;   // B stage: 32 rows x 16 float4
    const float* gA = X + (size_t)(m0 + ar) * EDIM + ac * 4;
    const float* gB = W + (size_t)br * EDIM + jo + bc * 4;

    u64 acc[4][4];
#pragma unroll
    for (int i = 0; i < 4; i++)
#pragma unroll
        for (int c = 0; c < 4; c++) acc[i][c] = 0ull;

    float4 ra[4], rb[2];

    // Prologue: chunk 0 -> buffer 0 (A transposed on store)
#pragma unroll
    for (int u = 0; u < 4; u++)
        ra[u] = *(const float4*)(gA + (size_t)u * 32 * EDIM);
#pragma unroll
    for (int u = 0; u < 2; u++)
        rb[u] = *(const float4*)(gB + (size_t)u * 16 * EDIM);
#pragma unroll
    for (int u = 0; u < 4; u++) {
        const int r = ar + 32 * u;
        sA[(ac * 4 + 0) * K1_SAP + r] = ra[u].x;
        sA[(ac * 4 + 1) * K1_SAP + r] = ra[u].y;
        sA[(ac * 4 + 2) * K1_SAP + r] = ra[u].z;
        sA[(ac * 4 + 3) * K1_SAP + r] = ra[u].w;
    }
#pragma unroll
    for (int u = 0; u < 2; u++)
        *(float4*)(sB + (br + 16 * u) * K1_SBP + bc * 4) = rb[u];
    __syncthreads();

#pragma unroll 1
    for (int kc = 0; kc < 8; kc++) {
        const int p = kc & 1;
        if (kc < 7) {
#pragma unroll
            for (int u = 0; u < 4; u++)
                ra[u] = *(const float4*)(gA + (kc + 1) * 32 + (size_t)u * 32 * EDIM);
#pragma unroll
            for (int u = 0; u < 2; u++)
                rb[u] = *(const float4*)(gB + (size_t)((kc + 1) * 32) * EDIM
                                             + (size_t)u * 16 * EDIM);
        }
        const float* Ap = sA + p * 32 * K1_SAP + ti * 8;
        const float* Bp = sB + p * 32 * K1_SBP + tj * 4;
#pragma unroll 8
        for (int kk = 0; kk < 32; kk++) {
            const ulonglong2 a01 = *(const ulonglong2*)(Ap + kk * K1_SAP);
            const ulonglong2 a23 = *(const ulonglong2*)(Ap + kk * K1_SAP + 4);
            const float4 bv = *(const float4*)(Bp + kk * K1_SBP);
            const u64 b0 = pack2(bv.x, bv.x);
            const u64 b1 = pack2(bv.y, bv.y);
            const u64 b2 = pack2(bv.z, bv.z);
            const u64 b3 = pack2(bv.w, bv.w);
            fma2(acc[0][0], a01.x, b0); fma2(acc[1][0], a01.y, b0);
            fma2(acc[2][0], a23.x, b0); fma2(acc[3][0], a23.y, b0);
            fma2(acc[0][1], a01.x, b1); fma2(acc[1][1], a01.y, b1);
            fma2(acc[2][1], a23.x, b1); fma2(acc[3][1], a23.y, b1);
            fma2(acc[0][2], a01.x, b2); fma2(acc[1][2], a01.y, b2);
            fma2(acc[2][2], a23.x, b2); fma2(acc[3][2], a23.y, b2);
            fma2(acc[0][3], a01.x, b3); fma2(acc[1][3], a01.y, b3);
            fma2(acc[2][3], a23.x, b3); fma2(acc[3][3], a23.y, b3);
        }
        if (kc < 7) {
            const int q = p ^ 1;
#pragma unroll
            for (int u = 0; u < 4; u++) {
                const int r = ar + 32 * u;
                float* d = sA + q * 32 * K1_SAP;
                d[(ac * 4 + 0) * K1_SAP + r] = ra[u].x;
                d[(ac * 4 + 1) * K1_SAP + r] = ra[u].y;
                d[(ac * 4 + 2) * K1_SAP + r] = ra[u].z;
                d[(ac * 4 + 3) * K1_SAP + r] = ra[u].w;
            }
#pragma unroll
            for (int u = 0; u < 2; u++)
                *(float4*)(sB + q * 32 * K1_SBP + (br + 16 * u) * K1_SBP + bc * 4) = rb[u];
            __syncthreads();
        }
    }

    // Epilogue: acc[i] holds rows (8ti+2i, 8ti+2i+1), cols 4tj..+3
    const int orow = m0 + ti * 8;
#pragma unroll
    for (int i = 0; i < 4; i++) {
        const float2 c0 = unpack2(acc[i][0]);
        const float2 c1 = unpack2(acc[i][1]);
        const float2 c2 = unpack2(acc[i][2]);
        const float2 c3 = unpack2(acc[i][3]);
        *(float4*)(out + (size_t)(orow + 2 * i) * EDIM + jo + tj * 4)
            = make_float4(c0.x, c1.x, c2.x, c3.x);
        *(float4*)(out + (size_t)(orow + 2 * i + 1) * EDIM + jo + tj * 4)
            = make_float4(c0.y, c1.y, c2.y, c3.y);
    }
}

// ---------------------------------------------------------------------------
// Kernel 2: per-(batch, head) attention.  Grid (8,1024), 512 threads.
//   sQT [32][132] : Q^T (dim-major) -> row-pair loads for FFMA2
//   sKT [32][132] : K^T (dim-major) -> float4 B loads
//   sV  [128][36] : V row-major (natural B layout for PV)
//   sS  [128][132]: scores -> unnormalized exp probabilities
//   sInv[128]     : 1/rowsum, folded into epilogue
// Softmax: 4 threads per row + shfl_xor(width=4) reduction.
// ---------------------------------------------------------------------------
constexpr int K2_SKP = 132;
constexpr int K2_SVP = 36;
constexpr int K2_SSP = 132;
constexpr int K2_SMEM =
    (2 * 32 * K2_SKP + 128 * K2_SVP + 128 * K2_SSP + 128) * 4;  // 120320 B

__global__ void __launch_bounds__(512, 1)
attn_kernel(float* __restrict__ out)
{
    extern __shared__ float sm2[];
    float* sQT  = sm2;                       // [32][132]
    float* sKT  = sQT + 32 * K2_SKP;         // [32][132]
    float* sV   = sKT + 32 * K2_SKP;         // [128][36]
    float* sS   = sV + 128 * K2_SVP;         // [128][132]
    float* sInv = sS + 128 * K2_SSP;         // [128]

    const int t = threadIdx.x;
    const int h = blockIdx.x;
    const int b = blockIdx.y;
    const size_t MN = (size_t)MROWS * EDIM;
    const float* Qg = g_QKVR + (size_t)b * FDIM * EDIM + h * DHEAD;
    const float* Kg = Qg + MN;
    const float* Vg = Qg + 2 * MN;
    const float* Rg = Qg + 3 * MN;

    // ---- Stage: Q,K transposed (dim-major), V row-major ----
    {
        const int ar = t >> 3, ac = t & 7;   // 64 rows x 8 float4, x2 steps
#pragma unroll
        for (int u = 0; u < 2; u++) {
            const int r = ar + 64 * u;
            const float4 q = *(const float4*)(Qg + (size_t)r * EDIM + ac * 4);
            const float4 k = *(const float4*)(Kg + (size_t)r * EDIM + ac * 4);
            const float4 v = *(const float4*)(Vg + (size_t)r * EDIM + ac * 4);
            *(float4*)(sV + r * K2_SVP + ac * 4) = v;
            sQT[(ac * 4 + 0) * K2_SKP + r] = q.x;
            sQT[(ac * 4 + 1) * K2_SKP + r] = q.y;
            sQT[(ac * 4 + 2) * K2_SKP + r] = q.z;
            sQT[(ac * 4 + 3) * K2_SKP + r] = q.w;
            sKT[(ac * 4 + 0) * K2_SKP + r] = k.x;
            sKT[(ac * 4 + 1) * K2_SKP + r] = k.y;
            sKT[(ac * 4 + 2) * K2_SKP + r] = k.z;
            sKT[(ac * 4 + 3) * K2_SKP + r] = k.w;
        }
    }
    __syncthreads();

    // ---- S = Q @ K^T (128x128, K=32): 16x32 thread grid, 8x4 tile ----
    {
        const int ti = t >> 5;   // 0..15 (constant per warp -> broadcast A)
        const int tj = t & 31;   // 0..31
        u64 acc[4][4];
#pragma unroll
        for (int i = 0; i < 4; i++)
#pragma unroll
            for (int c = 0; c < 4; c++) acc[i][c] = 0ull;

        const float* Ap = sQT + ti * 8;
        const float* Bp = sKT + tj * 4;
#pragma unroll 8
        for (int k = 0; k < 32; k++) {
            const ulonglong2 a01 = *(const ulonglong2*)(Ap + k * K2_SKP);
            const ulonglong2 a23 = *(const ulonglong2*)(Ap + k * K2_SKP + 4);
            const float4 bv = *(const float4*)(Bp + k * K2_SKP);
            const u64 b0 = pack2(bv.x, bv.x);
            const u64 b1 = pack2(bv.y, bv.y);
            const u64 b2 = pack2(bv.z, bv.z);
            const u64 b3 = pack2(bv.w, bv.w);
            fma2(acc[0][0], a01.x, b0); fma2(acc[1][0], a01.y, b0);
            fma2(acc[2][0], a23.x, b0); fma2(acc[3][0], a23.y, b0);
            fma2(acc[0][1], a01.x, b1); fma2(acc[1][1], a01.y, b1);
            fma2(acc[2][1], a23.x, b1); fma2(acc[3][1], a23.y, b1);
            fma2(acc[0][2], a01.x, b2); fma2(acc[1][2], a01.y, b2);
            fma2(acc[2][2], a23.x, b2); fma2(acc[3][2], a23.y, b2);
            fma2(acc[0][3], a01.x, b3); fma2(acc[1][3], a01.y, b3);
            fma2(acc[2][3], a23.x, b3); fma2(acc[3][3], a23.y, b3);
        }
        float* Sp = sS + (ti * 8) * K2_SSP + tj * 4;
#pragma unroll
        for (int i = 0; i < 4; i++) {
            const float2 c0 = unpack2(acc[i][0]);
            const float2 c1 = unpack2(acc[i][1]);
            const float2 c2 = unpack2(acc[i][2]);
            const float2 c3 = unpack2(acc[i][3]);
            *(float4*)(Sp + (2 * i) * K2_SSP)     = make_float4(c0.x, c1.x, c2.x, c3.x);
            *(float4*)(Sp + (2 * i + 1) * K2_SSP) = make_float4(c0.y, c1.y, c2.y, c3.y);
        }
    }
    __syncthreads();

    // ---- Row softmax: 4 threads/row, shfl_xor(width=4) reduction ----
    {
        const int row = t >> 2, seg = t & 3;
        float* rp = sS + row * K2_SSP + seg * 32;
        float mx = -3.402823e38f;
#pragma unroll
        for (int j = 0; j < 8; j++) {
            const float4 v = *(const float4*)(rp + j * 4);
            mx = fmaxf(mx, fmaxf(fmaxf(v.x, v.y), fmaxf(v.z, v.w)));
        }
        mx = fmaxf(mx, __shfl_xor_sync(0xffffffffu, mx, 1, 4));
        mx = fmaxf(mx, __shfl_xor_sync(0xffffffffu, mx, 2, 4));
        float sum = 0.f;
#pragma unroll
        for (int j = 0; j < 8; j++) {
            float4 v = *(const float4*)(rp + j * 4);
            v.x = __expf(v.x - mx); v.y = __expf(v.y - mx);
            v.z = __expf(v.z - mx); v.w = __expf(v.w - mx);
            sum += (v.x + v.y) + (v.z + v.w);
            *(float4*)(rp + j * 4) = v;
        }
        sum += __shfl_xor_sync(0xffffffffu, sum, 1, 4);
        sum += __shfl_xor_sync(0xffffffffu, sum, 2, 4);
        if (seg == 0) sInv[row] = 1.0f / sum;
    }
    __syncthreads();

    // ---- O = P @ V (128x32, K=128): 1 row x 8 cols per thread ----
    {
        const int row = t >> 2;      // 0..127
        const int tjv = t & 3;       // cols 8*tjv..8*tjv+7

        float4 rv0 = *(const float4*)(Rg + (size_t)row * EDIM + tjv * 8);
        float4 rv1 = *(const float4*)(Rg + (size_t)row * EDIM + tjv * 8 + 4);

        u64 acc[4];
#pragma unroll
        for (int c = 0; c < 4; c++) acc[c] = 0ull;

        const float* Ap = sS + row * K2_SSP;
        const float* Bp = sV + tjv * 8;
#pragma unroll 8
        for (int k = 0; k < 128; k++) {
            const float a = Ap[k];
            const u64 ap = pack2(a, a);
            const ulonglong2 b01 = *(const ulonglong2*)(Bp + k * K2_SVP);
            const ulonglong2 b23 = *(const ulonglong2*)(Bp + k * K2_SVP + 4);
            fma2(acc[0], ap, b01.x); fma2(acc[1], ap, b01.y);
            fma2(acc[2], ap, b23.x); fma2(acc[3], ap, b23.y);
        }

        const float inv = sInv[row];
        const float2 p0 = unpack2(acc[0]);
        const float2 p1 = unpack2(acc[1]);
        const float2 p2 = unpack2(acc[2]);
        const float2 p3 = unpack2(acc[3]);
        float4 o0, o1;
        o0.x = fmaxf(fmaf(p0.x, inv, rv0.x), 0.f);
        o0.y = fmaxf(fmaf(p0.y, inv, rv0.y), 0.f);
        o0.z = fmaxf(fmaf(p1.x, inv, rv0.z), 0.f);
        o0.w = fmaxf(fmaf(p1.y, inv, rv0.w), 0.f);
        o1.x = fmaxf(fmaf(p2.x, inv, rv1.x), 0.f);
        o1.y = fmaxf(fmaf(p2.y, inv, rv1.y), 0.f);
        o1.z = fmaxf(fmaf(p3.x, inv, rv1.z), 0.f);
        o1.w = fmaxf(fmaf(p3.y, inv, rv1.w), 0.f);

        float* ob = out + (size_t)b * FDIM * EDIM + h * DHEAD;
        *(float4*)(ob + (size_t)row * EDIM + tjv * 8)     = o0;
        *(float4*)(ob + (size_t)row * EDIM + tjv * 8 + 4) = o1;
    }
}

// ---------------------------------------------------------------------------
extern "C" void kernel_launch(void* const* d_in, const int* in_sizes, int n_in,
                              void* d_out, int out_size)
{
    const float* X  = (const float*)d_in[0];
    const float* Wq = (const float*)d_in[1];
    const float* Wk = (const float*)d_in[2];
    const float* Wv = (const float*)d_in[3];
    const float* Wr = (const float*)d_in[4];
    float* out = (float*)d_out;

    cudaFuncSetAttribute(proj_kernel, cudaFuncAttributeMaxDynamicSharedMemorySize, K1_SMEM);
    cudaFuncSetAttribute(attn_kernel, cudaFuncAttributeMaxDynamicSharedMemorySize, K2_SMEM);

    proj_kernel<<<dim3(16, 1024), 256, K1_SMEM>>>(X, Wq, Wk, Wv, Wr);
    attn_kernel<<<dim3(8, 1024), 512, K2_SMEM>>>(out);
}

// round 16
// speedup vs baseline: 1.1725x; 1.1725x over previous
#include <cuda_runtime.h>

// Problem constants
#define BATCH  1024
#define FDIM   128
#define EDIM   256
#define HEADS  8
#define DHEAD  32
#define MROWS  (BATCH * FDIM)   // 131072

// Scratch for Q, K, V, R projections: 4 * 131072 * 256 floats = 512 MB.
__device__ float g_QKVR[(size_t)4 * MROWS * EDIM];

typedef unsigned long long u64;

// ---- packed fp32 (FFMA2) helpers -----------------------------------------
__device__ __forceinline__ u64 pack2(float lo, float hi) {
    u64 r;
    asm("mov.b64 %0, {%1, %2};" : "=l"(r) : "f"(lo), "f"(hi));
    return r;
}
__device__ __forceinline__ void fma2(u64& d, u64 a, u64 b) {
    asm("fma.rn.f32x2 %0, %1, %2, %3;" : "=l"(d) : "l"(a), "l"(b), "l"(d));
}
__device__ __forceinline__ float2 unpack2(u64 v) {
    float2 f;
    asm("mov.b64 {%0, %1}, %2;" : "=f"(f.x), "=f"(f.y) : "l"(v));
    return f;
}

// ---------------------------------------------------------------------------
// Kernel 1: projections (R10, measured ~1350us).  C[128x64] = X[128x256]@W.
// Grid (16,1024), 256 threads, 2 CTAs/SM.  sA k-major for FFMA2 row-pairs.
// ---------------------------------------------------------------------------
constexpr int K1_SAP = 132;  // sA^T pitch: 128 rows + 4 pad
constexpr int K1_SBP = 68;   // sB pitch: 64 cols + 4 pad
constexpr int K1_SMEM = (2 * 32 * K1_SAP + 2 * 32 * K1_SBP) * 4;  // 51200 B

__global__ void __launch_bounds__(256, 2)
proj_kernel(const float* __restrict__ X,
            const float* __restrict__ Wq, const float* __restrict__ Wk,
            const float* __restrict__ Wv, const float* __restrict__ Wr)
{
    extern __shared__ float sm1[];
    float* sA = sm1;                      // [2][32 k][132 rows]
    float* sB = sm1 + 2 * 32 * K1_SAP;    // [2][32 k][68 cols]

    const int t    = threadIdx.x;
    const int bx   = blockIdx.x;
    const int m0   = blockIdx.y * 128;
    const int widx = bx >> 2;
    const int jo   = (bx & 3) * 64;
    const float* W = (widx == 0) ? Wq : (widx == 1) ? Wk : (widx == 2) ? Wv : Wr;
    float* out = g_QKVR + (size_t)widx * MROWS * EDIM;

    const int ti = t >> 4;
    const int tj = t & 15;

    const int ar = t >> 3, ac = t & 7;
    const int br = t >> 4, bc = t & 15;
    const float* gA = X + (size_t)(m0 + ar) * EDIM + ac * 4;
    const float* gB = W + (size_t)br * EDIM + jo + bc * 4;

    u64 acc[4][4];
#pragma unroll
    for (int i = 0; i < 4; i++)
#pragma unroll
        for (int c = 0; c < 4; c++) acc[i][c] = 0ull;

    float4 ra[4], rb[2];

#pragma unroll
    for (int u = 0; u < 4; u++)
        ra[u] = *(const float4*)(gA + (size_t)u * 32 * EDIM);
#pragma unroll
    for (int u = 0; u < 2; u++)
        rb[u] = *(const float4*)(gB + (size_t)u * 16 * EDIM);
#pragma unroll
    for (int u = 0; u < 4; u++) {
        const int r = ar + 32 * u;
        sA[(ac * 4 + 0) * K1_SAP + r] = ra[u].x;
        sA[(ac * 4 + 1) * K1_SAP + r] = ra[u].y;
        sA[(ac * 4 + 2) * K1_SAP + r] = ra[u].z;
        sA[(ac * 4 + 3) * K1_SAP + r] = ra[u].w;
    }
#pragma unroll
    for (int u = 0; u < 2; u++)
        *(float4*)(sB + (br + 16 * u) * K1_SBP + bc * 4) = rb[u];
    __syncthreads();

#pragma unroll 1
    for (int kc = 0; kc < 8; kc++) {
        const int p = kc & 1;
        if (kc < 7) {
#pragma unroll
            for (int u = 0; u < 4; u++)
                ra[u] = *(const float4*)(gA + (kc + 1) * 32 + (size_t)u * 32 * EDIM);
#pragma unroll
            for (int u = 0; u < 2; u++)
                rb[u] = *(const float4*)(gB + (size_t)((kc + 1) * 32) * EDIM
                                             + (size_t)u * 16 * EDIM);
        }
        const float* Ap = sA + p * 32 * K1_SAP + ti * 8;
        const float* Bp = sB + p * 32 * K1_SBP + tj * 4;
#pragma unroll 8
        for (int kk = 0; kk < 32; kk++) {
            const ulonglong2 a01 = *(const ulonglong2*)(Ap + kk * K1_SAP);
            const ulonglong2 a23 = *(const ulonglong2*)(Ap + kk * K1_SAP + 4);
            const float4 bv = *(const float4*)(Bp + kk * K1_SBP);
            const u64 b0 = pack2(bv.x, bv.x);
            const u64 b1 = pack2(bv.y, bv.y);
            const u64 b2 = pack2(bv.z, bv.z);
            const u64 b3 = pack2(bv.w, bv.w);
            fma2(acc[0][0], a01.x, b0); fma2(acc[1][0], a01.y, b0);
            fma2(acc[2][0], a23.x, b0); fma2(acc[3][0], a23.y, b0);
            fma2(acc[0][1], a01.x, b1); fma2(acc[1][1], a01.y, b1);
            fma2(acc[2][1], a23.x, b1); fma2(acc[3][1], a23.y, b1);
            fma2(acc[0][2], a01.x, b2); fma2(acc[1][2], a01.y, b2);
            fma2(acc[2][2], a23.x, b2); fma2(acc[3][2], a23.y, b2);
            fma2(acc[0][3], a01.x, b3); fma2(acc[1][3], a01.y, b3);
            fma2(acc[2][3], a23.x, b3); fma2(acc[3][3], a23.y, b3);
        }
        if (kc < 7) {
            const int q = p ^ 1;
#pragma unroll
            for (int u = 0; u < 4; u++) {
                const int r = ar + 32 * u;
                float* d = sA + q * 32 * K1_SAP;
                d[(ac * 4 + 0) * K1_SAP + r] = ra[u].x;
                d[(ac * 4 + 1) * K1_SAP + r] = ra[u].y;
                d[(ac * 4 + 2) * K1_SAP + r] = ra[u].z;
                d[(ac * 4 + 3) * K1_SAP + r] = ra[u].w;
            }
#pragma unroll
            for (int u = 0; u < 2; u++)
                *(float4*)(sB + q * 32 * K1_SBP + (br + 16 * u) * K1_SBP + bc * 4) = rb[u];
            __syncthreads();
        }
    }

    const int orow = m0 + ti * 8;
#pragma unroll
    for (int i = 0; i < 4; i++) {
        const float2 c0 = unpack2(acc[i][0]);
        const float2 c1 = unpack2(acc[i][1]);
        const float2 c2 = unpack2(acc[i][2]);
        const float2 c3 = unpack2(acc[i][3]);
        *(float4*)(out + (size_t)(orow + 2 * i) * EDIM + jo + tj * 4)
            = make_float4(c0.x, c1.x, c2.x, c3.x);
        *(float4*)(out + (size_t)(orow + 2 * i + 1) * EDIM + jo + tj * 4)
            = make_float4(c0.y, c1.y, c2.y, c3.y);
    }
}

// ---------------------------------------------------------------------------
// Kernel 2: attention — R7 structure/layout/loads (measured 591us) with FFMA2
// applied WITHOUT changing any memory access: B col-pairs come free from the
// existing 128-bit loads (reinterpret as ulonglong2); A scalars dup via pack2.
// Grid (8,1024), 256 threads.
//   sQ  [128][36], sKT [32][132], sV [128][36], sS [128][132], sInv[128]
// ---------------------------------------------------------------------------
constexpr int K2_SQP = 36;
constexpr int K2_SKP = 132;
constexpr int K2_SVP = 36;
constexpr int K2_SSP = 132;
constexpr int K2_SMEM =
    (128 * K2_SQP + 32 * K2_SKP + 128 * K2_SVP + 128 * K2_SSP + 128) * 4;  // 121856 B

__global__ void __launch_bounds__(256, 1)
attn_kernel(float* __restrict__ out)
{
    extern __shared__ float sm2[];
    float* sQ   = sm2;
    float* sKT  = sQ + 128 * K2_SQP;
    float* sV   = sKT + 32 * K2_SKP;
    float* sS   = sV + 128 * K2_SVP;
    float* sInv = sS + 128 * K2_SSP;

    const int t = threadIdx.x;
    const int h = blockIdx.x;
    const int b = blockIdx.y;
    const size_t MN = (size_t)MROWS * EDIM;
    const float* Qg = g_QKVR + (size_t)b * FDIM * EDIM + h * DHEAD;
    const float* Kg = Qg + MN;
    const float* Vg = Qg + 2 * MN;
    const float* Rg = Qg + 3 * MN;

    // ---- Stage Q, V (row-major) and K (transposed k-major) ----
    {
        const int r0 = t >> 3, c4 = t & 7;
#pragma unroll
        for (int u = 0; u < 4; u++) {
            const int r = r0 + 32 * u;
            const float4 q = *(const float4*)(Qg + (size_t)r * EDIM + c4 * 4);
            const float4 k = *(const float4*)(Kg + (size_t)r * EDIM + c4 * 4);
            const float4 v = *(const float4*)(Vg + (size_t)r * EDIM + c4 * 4);
            *(float4*)(sQ + r * K2_SQP + c4 * 4) = q;
            *(float4*)(sV + r * K2_SVP + c4 * 4) = v;
            sKT[(c4 * 4 + 0) * K2_SKP + r] = k.x;
            sKT[(c4 * 4 + 1) * K2_SKP + r] = k.y;
            sKT[(c4 * 4 + 2) * K2_SKP + r] = k.z;
            sKT[(c4 * 4 + 3) * K2_SKP + r] = k.w;
        }
    }
    __syncthreads();

    // ---- S = Q @ K^T (128x128, K=32): 16x16 grid, 8x8 tile, FFMA2 pairs ----
    {
        const int ti = t >> 4, tj = t & 15;
        u64 acc[8][4];   // 8 rows x 4 col-pairs
#pragma unroll
        for (int r = 0; r < 8; r++)
#pragma unroll
            for (int c = 0; c < 4; c++) acc[r][c] = 0ull;

        const float* Ap = sQ + ti * 8 * K2_SQP;
        const float* Bp = sKT + tj * 8;
#pragma unroll 4
        for (int k = 0; k < 32; k++) {
            // A: 8 scalar loads (identical addresses to R7), duplicated
            u64 a[8];
#pragma unroll
            for (int r = 0; r < 8; r++) {
                const float av = Ap[r * K2_SQP + k];
                a[r] = pack2(av, av);
            }
            // B: same two 128-bit loads as R7, reinterpreted as col-pairs
            const ulonglong2 b01 = *(const ulonglong2*)(Bp + k * K2_SKP);
            const ulonglong2 b23 = *(const ulonglong2*)(Bp + k * K2_SKP + 4);
#pragma unroll
            for (int r = 0; r < 8; r++) {
                fma2(acc[r][0], a[r], b01.x);
                fma2(acc[r][1], a[r], b01.y);
                fma2(acc[r][2], a[r], b23.x);
                fma2(acc[r][3], a[r], b23.y);
            }
        }
        float* Sp = sS + ti * 8 * K2_SSP + tj * 8;
#pragma unroll
        for (int r = 0; r < 8; r++) {
            const float2 p0 = unpack2(acc[r][0]);
            const float2 p1 = unpack2(acc[r][1]);
            const float2 p2 = unpack2(acc[r][2]);
            const float2 p3 = unpack2(acc[r][3]);
            *(float4*)(Sp + r * K2_SSP)     = make_float4(p0.x, p0.y, p1.x, p1.y);
            *(float4*)(Sp + r * K2_SSP + 4) = make_float4(p2.x, p2.y, p3.x, p3.y);
        }
    }
    __syncthreads();

    // ---- Row softmax (R7): 1 thread/row, unnormalized exp + 1/sum ----
    if (t < 128) {
        float* row = sS + t * K2_SSP;
        float mx = -3.402823e38f;
#pragma unroll 8
        for (int j = 0; j < 32; j++) {
            const float4 v = *(const float4*)(row + j * 4);
            mx = fmaxf(mx, fmaxf(fmaxf(v.x, v.y), fmaxf(v.z, v.w)));
        }
        float sum = 0.f;
#pragma unroll 8
        for (int j = 0; j < 32; j++) {
            float4 v = *(const float4*)(row + j * 4);
            v.x = __expf(v.x - mx); v.y = __expf(v.y - mx);
            v.z = __expf(v.z - mx); v.w = __expf(v.w - mx);
            sum += (v.x + v.y) + (v.z + v.w);
            *(float4*)(row + j * 4) = v;
        }
        sInv[t] = 1.0f / sum;
    }
    __syncthreads();

    // ---- O = P @ V (128x32, K=128): 32x8 grid, 4x4 tile, FFMA2 pairs ----
    {
        const int ti = t >> 3, tj = t & 7;
        u64 acc[4][2];   // 4 rows x 2 col-pairs
#pragma unroll
        for (int r = 0; r < 4; r++) { acc[r][0] = 0ull; acc[r][1] = 0ull; }

        // Prefetch residual slice (hides LDG latency behind the GEMM)
        float4 rv[4];
#pragma unroll
        for (int r = 0; r < 4; r++)
            rv[r] = *(const float4*)(Rg + (size_t)(ti * 4 + r) * EDIM + tj * 4);

        const float* Ap = sS + ti * 4 * K2_SSP;
        const float* Bp = sV + tj * 4;
#pragma unroll 8
        for (int k = 0; k < 128; k++) {
            // B: same 128-bit load as R7, reinterpreted as 2 col-pairs
            const ulonglong2 bp = *(const ulonglong2*)(Bp + k * K2_SVP);
            u64 a[4];
#pragma unroll
            for (int r = 0; r < 4; r++) {
                const float av = Ap[r * K2_SSP + k];
                a[r] = pack2(av, av);
            }
#pragma unroll
            for (int r = 0; r < 4; r++) {
                fma2(acc[r][0], a[r], bp.x);
                fma2(acc[r][1], a[r], bp.y);
            }
        }

        float* ob = out + (size_t)b * FDIM * EDIM + h * DHEAD;
#pragma unroll
        for (int r = 0; r < 4; r++) {
            const int row = ti * 4 + r;
            const float inv = sInv[row];
            const float2 p0 = unpack2(acc[r][0]);
            const float2 p1 = unpack2(acc[r][1]);
            float4 o;
            o.x = fmaxf(fmaf(p0.x, inv, rv[r].x), 0.f);
            o.y = fmaxf(fmaf(p0.y, inv, rv[r].y), 0.f);
            o.z = fmaxf(fmaf(p1.x, inv, rv[r].z), 0.f);
            o.w = fmaxf(fmaf(p1.y, inv, rv[r].w), 0.f);
            *(float4*)(ob + (size_t)row * EDIM + tj * 4) = o;
        }
    }
}

// ---------------------------------------------------------------------------
extern "C" void kernel_launch(void* const* d_in, const int* in_sizes, int n_in,
                              void* d_out, int out_size)
{
    const float* X  = (const float*)d_in[0];
    const float* Wq = (const float*)d_in[1];
    const float* Wk = (const float*)d_in[2];
    const float* Wv = (const float*)d_in[3];
    const float* Wr = (const float*)d_in[4];
    float* out = (float*)d_out;

    cudaFuncSetAttribute(proj_kernel, cudaFuncAttributeMaxDynamicSharedMemorySize, K1_SMEM);
    cudaFuncSetAttribute(attn_kernel, cudaFuncAttributeMaxDynamicSharedMemorySize, K2_SMEM);

    proj_kernel<<<dim3(16, 1024), 256, K1_SMEM>>>(X, Wq, Wk, Wv, Wr);
    attn_kernel<<<dim3(8, 1024), 256, K2_SMEM>>>(out);
}